// round 3
// baseline (speedup 1.0000x reference)
#include <cuda_runtime.h>
#include <cuda_fp16.h>

#define N_NODES 100000
#define E_EDGES 1600000
#define IN_DIM 32
#define HID 64
#define NHEADS 2
#define F1 128   // NHEADS*HID
#define OUTC 64

// ---------------- scratch (device globals; no allocation allowed) ------------
__device__ __align__(16) __half g_h1h [(size_t)N_NODES * F1];   // 25.6 MB (gathered, fp16)
__device__ __align__(16) float  g_hln [(size_t)N_NODES * F1];   // 51.2 MB (proj2 input, fp32)
__device__ __align__(16) __half g_h2h [(size_t)N_NODES * OUTC]; // 12.8 MB (gathered, fp16)
__device__ __align__(8)  float g_as1[N_NODES * NHEADS];
__device__ __align__(8)  float g_ad1[N_NODES * NHEADS];
__device__ float g_as2[N_NODES];
__device__ float g_ad2[N_NODES];
__device__ int   g_deg[N_NODES];
__device__ int   g_off[N_NODES];
__device__ int   g_cur[N_NODES];
__device__ int   g_csr[E_EDGES];
__device__ int   g_bsum[256];
__device__ int   g_bscan[256];
__device__ float g_was1[IN_DIM * NHEADS];
__device__ float g_wad1[IN_DIM * NHEADS];
__device__ float g_was2[F1];
__device__ float g_wad2[F1];

__device__ __forceinline__ float lrelu(float v) { return v > 0.f ? v : 0.2f * v; }

// ---- packed fp32x2 helpers (sm_103a; PTX-only, ptxas won't auto-fuse) -------
__device__ __forceinline__ unsigned long long packdup(float a) {
    unsigned long long r;
    asm("mov.b64 %0, {%1, %1};" : "=l"(r) : "f"(a));
    return r;
}
__device__ __forceinline__ void ffma2(unsigned long long& acc,
                                      unsigned long long a, unsigned long long b) {
    asm("fma.rn.f32x2 %0, %1, %2, %0;" : "+l"(acc) : "l"(a), "l"(b));
}
__device__ __forceinline__ float lo32(unsigned long long v) {
    return __uint_as_float((unsigned)(v & 0xffffffffull));
}
__device__ __forceinline__ float hi32(unsigned long long v) {
    return __uint_as_float((unsigned)(v >> 32));
}

// ---------------- fold attention vectors into the linear weights -------------
__global__ void k_fold(const float* __restrict__ W1,
                       const float* __restrict__ as1, const float* __restrict__ ad1,
                       const float* __restrict__ W2,
                       const float* __restrict__ as2, const float* __restrict__ ad2) {
    int t = threadIdx.x;  // 128 threads
    if (t < IN_DIM * NHEADS) {
        int k = t & (IN_DIM - 1), h = t >> 5;
        float s = 0.f, d = 0.f;
        for (int c = 0; c < HID; ++c) {
            float w = W1[k * F1 + h * HID + c];
            s += w * as1[h * HID + c];
            d += w * ad1[h * HID + c];
        }
        g_was1[k * NHEADS + h] = s;
        g_wad1[k * NHEADS + h] = d;
    }
    if (t < F1) {
        float s = 0.f, d = 0.f;
        for (int c = 0; c < OUTC; ++c) {
            float w = W2[t * OUTC + c];
            s += w * as2[c];
            d += w * ad2[c];
        }
        g_was2[t] = s;
        g_wad2[t] = d;
    }
}

// ---------------- CSR build ---------------------------------------------------
__global__ void k_deg(const int* __restrict__ dst, int E) {
    int e = blockIdx.x * blockDim.x + threadIdx.x;
    if (e < E) atomicAdd(&g_deg[dst[e]], 1);
}

__global__ void k_scanA(int n) {
    __shared__ int wsum[8];
    int t = threadIdx.x;                 // 256
    int base = blockIdx.x * 1024;
    int s = 0;
    #pragma unroll
    for (int i = 0; i < 4; ++i) {
        int idx = base + t * 4 + i;
        if (idx < n) s += g_deg[idx];
    }
    #pragma unroll
    for (int o = 16; o > 0; o >>= 1) s += __shfl_xor_sync(0xffffffffu, s, o);
    if ((t & 31) == 0) wsum[t >> 5] = s;
    __syncthreads();
    if (t == 0) {
        int tot = 0;
        #pragma unroll
        for (int i = 0; i < 8; ++i) tot += wsum[i];
        g_bsum[blockIdx.x] = tot;
    }
}

__global__ void k_scanB(int nb) {
    __shared__ int ws[4];
    int t = threadIdx.x;                 // 128
    int v = (t < nb) ? g_bsum[t] : 0;
    int lane = t & 31, w = t >> 5;
    int s = v;
    #pragma unroll
    for (int o = 1; o < 32; o <<= 1) {
        int x = __shfl_up_sync(0xffffffffu, s, o);
        if (lane >= o) s += x;
    }
    if (lane == 31) ws[w] = s;
    __syncthreads();
    if (t < 4) {
        int x = ws[t];
        #pragma unroll
        for (int o = 1; o < 4; o <<= 1) {
            int y = __shfl_up_sync(0xfu, x, o);
            if (t >= o) x += y;
        }
        ws[t] = x;
    }
    __syncthreads();
    int incl = s + (w > 0 ? ws[w - 1] : 0);
    if (t < nb) g_bscan[t] = incl - v;
}

__global__ void k_scanC(int n) {
    __shared__ int wsum[8];
    int t = threadIdx.x;                 // 256
    int base = blockIdx.x * 1024;
    int v[4]; int s = 0;
    #pragma unroll
    for (int i = 0; i < 4; ++i) {
        int idx = base + t * 4 + i;
        v[i] = (idx < n) ? g_deg[idx] : 0;
        s += v[i];
    }
    int lane = t & 31, w = t >> 5;
    int incl = s;
    #pragma unroll
    for (int o = 1; o < 32; o <<= 1) {
        int x = __shfl_up_sync(0xffffffffu, incl, o);
        if (lane >= o) incl += x;
    }
    if (lane == 31) wsum[w] = incl;
    __syncthreads();
    if (t < 8) {
        int x = wsum[t];
        #pragma unroll
        for (int o = 1; o < 8; o <<= 1) {
            int y = __shfl_up_sync(0xffu, x, o);
            if (t >= o) x += y;
        }
        wsum[t] = x;
    }
    __syncthreads();
    int excl = incl - s + (w > 0 ? wsum[w - 1] : 0) + g_bscan[blockIdx.x];
    #pragma unroll
    for (int i = 0; i < 4; ++i) {
        int idx = base + t * 4 + i;
        if (idx < n) { g_off[idx] = excl; g_cur[idx] = excl; excl += v[i]; }
    }
}

__global__ void k_scatter(const int* __restrict__ src, const int* __restrict__ dst, int E) {
    int e = blockIdx.x * blockDim.x + threadIdx.x;
    if (e >= E) return;
    int d = dst[e];
    int pos = atomicAdd(&g_cur[d], 1);
    g_csr[pos] = src[e];
}

// ---------------- layer-1 projection: h1(fp16) = x @ W1, plus logits ---------
// f32x2 packed FMA; block = 32 nodes x 128 cols, 256 threads, thread 4x4.
__global__ void k1_proj(const float* __restrict__ x, const float* __restrict__ W1, int n) {
    __shared__ __align__(16) float Ws[IN_DIM * F1];     // 16 KB
    __shared__ __align__(16) float xsT[IN_DIM][36];     // k-major, stride 36 (16B-aligned rows)
    int t = threadIdx.x;                                // 256
    for (int i = t; i < IN_DIM * F1; i += 256) Ws[i] = W1[i];
    int base = blockIdx.x * 32;
    #pragma unroll
    for (int i = 0; i < 4; ++i) {
        int idx = t + i * 256;
        int node = idx >> 5, k = idx & 31;
        int nn = base + node;
        xsT[k][node] = (nn < n) ? x[(size_t)nn * IN_DIM + k] : 0.f;
    }
    __syncthreads();
    int tx = t & 31;        // col-pair group: cols tx*4 .. +3
    int ty = t >> 5;        // node group: nodes ty*4 .. +3
    unsigned long long acc[4][2] = {};
    #pragma unroll
    for (int k = 0; k < IN_DIM; ++k) {
        ulonglong2 w = *(const ulonglong2*)&Ws[k * F1 + tx * 4];
        float4 xv = *(const float4*)&xsT[k][ty * 4];
        unsigned long long xp0 = packdup(xv.x), xp1 = packdup(xv.y);
        unsigned long long xp2 = packdup(xv.z), xp3 = packdup(xv.w);
        ffma2(acc[0][0], w.x, xp0); ffma2(acc[0][1], w.y, xp0);
        ffma2(acc[1][0], w.x, xp1); ffma2(acc[1][1], w.y, xp1);
        ffma2(acc[2][0], w.x, xp2); ffma2(acc[2][1], w.y, xp2);
        ffma2(acc[3][0], w.x, xp3); ffma2(acc[3][1], w.y, xp3);
    }
    #pragma unroll
    for (int i = 0; i < 4; ++i) {
        int nn = base + ty * 4 + i;
        if (nn >= n) continue;
        __half2* hp = (__half2*)(g_h1h + (size_t)nn * F1 + tx * 4);
        hp[0] = __floats2half2_rn(lo32(acc[i][0]), hi32(acc[i][0]));
        hp[1] = __floats2half2_rn(lo32(acc[i][1]), hi32(acc[i][1]));
    }
    // layer-1 logits
    if (t < 128) {
        int node = t >> 2, sel = t & 3;
        int nn = base + node;
        if (nn < n) {
            const float* fv = (sel < 2) ? g_was1 : g_wad1;
            int h = sel & 1;
            float a = 0.f;
            #pragma unroll
            for (int k = 0; k < IN_DIM; ++k) a += xsT[k][node] * fv[k * NHEADS + h];
            if (sel < 2) g_as1[nn * 2 + h] = a;
            else         g_ad1[nn * 2 + h] = a;
        }
    }
}

// ------- layer-1 gather + normalize + LN + ReLU + layer-2 logits (fused) -----
__global__ void k_gather1(const float* __restrict__ bias1,
                          const float* __restrict__ gamma,
                          const float* __restrict__ beta, int n) {
    int node = (blockIdx.x * blockDim.x + threadIdx.x) >> 5;
    if (node >= n) return;
    int lane = threadIdx.x & 31;
    float2 lad = *(const float2*)&g_ad1[2 * node];
    float a0 = 0.f, a1 = 0.f, a2 = 0.f, a3 = 0.f, s0 = 0.f, s1 = 0.f;
    float b0 = 0.f, b1 = 0.f, b2 = 0.f, b3 = 0.f, t0 = 0.f, t1 = 0.f;
    // self-loop
    {
        float2 las = *(const float2*)&g_as1[2 * node];
        float w0 = __expf(lrelu(las.x + lad.x));
        float w1 = __expf(lrelu(las.y + lad.y));
        const __half2* hp = (const __half2*)(g_h1h + (size_t)node * F1);
        float2 fa = __half22float2(hp[lane]);
        float2 fb = __half22float2(hp[lane + 32]);
        a0 += w0 * fa.x; a1 += w0 * fa.y; a2 += w1 * fb.x; a3 += w1 * fb.y;
        s0 += w0; s1 += w1;
    }
    int beg = g_off[node], end = g_cur[node];
    int e = beg;
    for (; e + 1 < end; e += 2) {
        int sA = g_csr[e], sB = g_csr[e + 1];
        float2 lsA = *(const float2*)&g_as1[2 * sA];
        float2 lsB = *(const float2*)&g_as1[2 * sB];
        const __half2* hpA = (const __half2*)(g_h1h + (size_t)sA * F1);
        const __half2* hpB = (const __half2*)(g_h1h + (size_t)sB * F1);
        __half2 rA0 = hpA[lane], rA1 = hpA[lane + 32];
        __half2 rB0 = hpB[lane], rB1 = hpB[lane + 32];
        float wA0 = __expf(lrelu(lsA.x + lad.x));
        float wA1 = __expf(lrelu(lsA.y + lad.y));
        float wB0 = __expf(lrelu(lsB.x + lad.x));
        float wB1 = __expf(lrelu(lsB.y + lad.y));
        float2 fA0 = __half22float2(rA0), fA1 = __half22float2(rA1);
        float2 fB0 = __half22float2(rB0), fB1 = __half22float2(rB1);
        a0 += wA0 * fA0.x; a1 += wA0 * fA0.y; a2 += wA1 * fA1.x; a3 += wA1 * fA1.y;
        s0 += wA0; s1 += wA1;
        b0 += wB0 * fB0.x; b1 += wB0 * fB0.y; b2 += wB1 * fB1.x; b3 += wB1 * fB1.y;
        t0 += wB0; t1 += wB1;
    }
    if (e < end) {
        int sA = g_csr[e];
        float2 lsA = *(const float2*)&g_as1[2 * sA];
        float w0 = __expf(lrelu(lsA.x + lad.x));
        float w1 = __expf(lrelu(lsA.y + lad.y));
        const __half2* hp = (const __half2*)(g_h1h + (size_t)sA * F1);
        float2 fa = __half22float2(hp[lane]);
        float2 fb = __half22float2(hp[lane + 32]);
        a0 += w0 * fa.x; a1 += w0 * fa.y; a2 += w1 * fb.x; a3 += w1 * fb.y;
        s0 += w0; s1 += w1;
    }
    a0 += b0; a1 += b1; a2 += b2; a3 += b3; s0 += t0; s1 += t1;

    int c0 = 2 * lane, c2 = 2 * lane + 64;
    float r0 = 1.f / s0, r1 = 1.f / s1;
    float v0 = a0 * r0 + bias1[c0];
    float v1 = a1 * r0 + bias1[c0 + 1];
    float v2 = a2 * r1 + bias1[c2];
    float v3 = a3 * r1 + bias1[c2 + 1];
    // LayerNorm over 128 channels
    float tot = v0 + v1 + v2 + v3;
    #pragma unroll
    for (int o = 16; o > 0; o >>= 1) tot += __shfl_xor_sync(0xffffffffu, tot, o);
    float mu = tot * (1.f / 128.f);
    float d0 = v0 - mu, d1 = v1 - mu, d2 = v2 - mu, d3 = v3 - mu;
    float sq = d0 * d0 + d1 * d1 + d2 * d2 + d3 * d3;
    #pragma unroll
    for (int o = 16; o > 0; o >>= 1) sq += __shfl_xor_sync(0xffffffffu, sq, o);
    float inv = rsqrtf(sq * (1.f / 128.f) + 1e-5f);
    float y0 = fmaxf(d0 * inv * gamma[c0]     + beta[c0],     0.f);
    float y1 = fmaxf(d1 * inv * gamma[c0 + 1] + beta[c0 + 1], 0.f);
    float y2 = fmaxf(d2 * inv * gamma[c2]     + beta[c2],     0.f);
    float y3 = fmaxf(d3 * inv * gamma[c2 + 1] + beta[c2 + 1], 0.f);
    float* op = g_hln + (size_t)node * F1;
    *(float2*)&op[c0] = make_float2(y0, y1);
    *(float2*)&op[c2] = make_float2(y2, y3);
    // layer-2 logits from registers
    float sa = y0 * g_was2[c0] + y1 * g_was2[c0 + 1] + y2 * g_was2[c2] + y3 * g_was2[c2 + 1];
    float sd = y0 * g_wad2[c0] + y1 * g_wad2[c0 + 1] + y2 * g_wad2[c2] + y3 * g_wad2[c2 + 1];
    #pragma unroll
    for (int o = 16; o > 0; o >>= 1) {
        sa += __shfl_xor_sync(0xffffffffu, sa, o);
        sd += __shfl_xor_sync(0xffffffffu, sd, o);
    }
    if (lane == 0) { g_as2[node] = sa; g_ad2[node] = sd; }
}

// ---------------- layer-2 projection: h2(fp16) = hln(fp32) @ W2 --------------
// f32x2 packed FMA; block = 32 nodes x 64 cols, 128 threads, thread 4x4.
__global__ void k4_proj(const float* __restrict__ W2, int n) {
    __shared__ __align__(16) float Ws[F1 * OUTC];       // 32 KB
    __shared__ __align__(16) float xsT[F1 * 32];        // 16 KB (k-major, stride 32)
    int t = threadIdx.x;                                // 128
    for (int i = t; i < F1 * OUTC; i += 128) Ws[i] = W2[i];
    int base = blockIdx.x * 32;
    #pragma unroll
    for (int i = 0; i < 8; ++i) {
        int idx = t + i * 128;                          // 0..1023
        int node = idx & 31, k4 = idx >> 5;             // k4: 0..31 -> k = k4*4..+3
        int nn = base + node;
        float4 v = (nn < n) ? *(const float4*)&g_hln[(size_t)nn * F1 + k4 * 4]
                            : make_float4(0.f, 0.f, 0.f, 0.f);
        xsT[(k4 * 4 + 0) * 32 + node] = v.x;
        xsT[(k4 * 4 + 1) * 32 + node] = v.y;
        xsT[(k4 * 4 + 2) * 32 + node] = v.z;
        xsT[(k4 * 4 + 3) * 32 + node] = v.w;
    }
    __syncthreads();
    int tx = t & 15;   // cols tx*4 .. +3
    int ty = t >> 4;   // nodes ty*4 .. +3
    unsigned long long acc[4][2] = {};
    #pragma unroll 4
    for (int k = 0; k < F1; ++k) {
        ulonglong2 w = *(const ulonglong2*)&Ws[k * OUTC + tx * 4];
        const float* xr = &xsT[k * 32 + ty * 4];
        unsigned long long xp0 = packdup(xr[0]), xp1 = packdup(xr[1]);
        unsigned long long xp2 = packdup(xr[2]), xp3 = packdup(xr[3]);
        ffma2(acc[0][0], w.x, xp0); ffma2(acc[0][1], w.y, xp0);
        ffma2(acc[1][0], w.x, xp1); ffma2(acc[1][1], w.y, xp1);
        ffma2(acc[2][0], w.x, xp2); ffma2(acc[2][1], w.y, xp2);
        ffma2(acc[3][0], w.x, xp3); ffma2(acc[3][1], w.y, xp3);
    }
    #pragma unroll
    for (int i = 0; i < 4; ++i) {
        int nn = base + ty * 4 + i;
        if (nn >= n) continue;
        __half2* hp = (__half2*)(g_h2h + (size_t)nn * OUTC + tx * 4);
        hp[0] = __floats2half2_rn(lo32(acc[i][0]), hi32(acc[i][0]));
        hp[1] = __floats2half2_rn(lo32(acc[i][1]), hi32(acc[i][1]));
    }
}

// ---------------- layer-2 gather + finalize ----------------------------------
__global__ void k_gather2(float* __restrict__ out, const float* __restrict__ bias2, int n) {
    int node = (blockIdx.x * blockDim.x + threadIdx.x) >> 5;
    if (node >= n) return;
    int lane = threadIdx.x & 31;
    float lad = g_ad2[node];
    float ax = 0.f, ay = 0.f, ssum = 0.f;
    float bx = 0.f, by = 0.f, tsum = 0.f;
    {
        float w = __expf(lrelu(g_as2[node] + lad));
        float2 f = __half22float2(((const __half2*)(g_h2h + (size_t)node * OUTC))[lane]);
        ax += w * f.x; ay += w * f.y; ssum += w;
    }
    int beg = g_off[node], end = g_cur[node];
    int e = beg;
    for (; e + 1 < end; e += 2) {
        int sA = g_csr[e], sB = g_csr[e + 1];
        float lsA = g_as2[sA], lsB = g_as2[sB];
        __half2 rA = ((const __half2*)(g_h2h + (size_t)sA * OUTC))[lane];
        __half2 rB = ((const __half2*)(g_h2h + (size_t)sB * OUTC))[lane];
        float wA = __expf(lrelu(lsA + lad));
        float wB = __expf(lrelu(lsB + lad));
        float2 fA = __half22float2(rA), fB = __half22float2(rB);
        ax += wA * fA.x; ay += wA * fA.y; ssum += wA;
        bx += wB * fB.x; by += wB * fB.y; tsum += wB;
    }
    if (e < end) {
        int sA = g_csr[e];
        float w = __expf(lrelu(g_as2[sA] + lad));
        float2 f = __half22float2(((const __half2*)(g_h2h + (size_t)sA * OUTC))[lane]);
        ax += w * f.x; ay += w * f.y; ssum += w;
    }
    ax += bx; ay += by; ssum += tsum;
    float r = 1.f / ssum;
    float2 o;
    o.x = ax * r + bias2[2 * lane];
    o.y = ay * r + bias2[2 * lane + 1];
    ((float2*)out)[(size_t)node * 32 + lane] = o;
}

// ---------------- launcher -----------------------------------------------------
extern "C" void kernel_launch(void* const* d_in, const int* in_sizes, int n_in,
                              void* d_out, int out_size) {
    const float* x     = (const float*)d_in[0];
    const int*   ei    = (const int*)  d_in[1];
    const float* W1    = (const float*)d_in[2];
    const float* as1   = (const float*)d_in[3];
    const float* ad1   = (const float*)d_in[4];
    const float* b1    = (const float*)d_in[5];
    const float* gamma = (const float*)d_in[6];
    const float* beta  = (const float*)d_in[7];
    const float* W2    = (const float*)d_in[8];
    const float* as2   = (const float*)d_in[9];
    const float* ad2   = (const float*)d_in[10];
    const float* b2    = (const float*)d_in[11];
    float* out = (float*)d_out;

    int n = in_sizes[0] / IN_DIM;
    int E = in_sizes[1] / 2;
    const int* srcp = ei;
    const int* dstp = ei + E;
    int nb = (n + 1023) / 1024;

    void* p;
    cudaGetSymbolAddress(&p, g_deg);
    cudaMemsetAsync(p, 0, (size_t)n * sizeof(int));

    // CSR build
    k_deg<<<(E + 255) / 256, 256>>>(dstp, E);
    k_scanA<<<nb, 256>>>(n);
    k_scanB<<<1, 128>>>(nb);
    k_scanC<<<nb, 256>>>(n);
    k_scatter<<<(E + 255) / 256, 256>>>(srcp, dstp, E);

    // compute
    k_fold<<<1, 128>>>(W1, as1, ad1, W2, as2, ad2);
    k1_proj<<<(n + 31) / 32, 256>>>(x, W1, n);
    k_gather1<<<(n + 7) / 8, 256>>>(b1, gamma, beta, n);
    k4_proj<<<(n + 31) / 32, 128>>>(W2, n);
    k_gather2<<<(n + 7) / 8, 256>>>(out, b2, n);
}

// round 4
// speedup vs baseline: 1.1193x; 1.1193x over previous
#include <cuda_runtime.h>
#include <cuda_fp16.h>

#define N_NODES 100000
#define E_EDGES 1600000
#define IN_DIM 32
#define HID 64
#define NHEADS 2
#define F1 128   // NHEADS*HID
#define OUTC 64

#define CSR_BLOCKS 512
#define CSR_THREADS 256

// ---------------- scratch (device globals; no allocation allowed) ------------
__device__ __align__(16) __half g_h1h [(size_t)N_NODES * F1];   // 25.6 MB
__device__ __align__(16) __half g_hlnh[(size_t)N_NODES * F1];   // 25.6 MB
__device__ __align__(16) __half g_h2h [(size_t)N_NODES * OUTC]; // 12.8 MB
__device__ __align__(8)  float g_as1[N_NODES * NHEADS];
__device__ __align__(8)  float g_ad1[N_NODES * NHEADS];
__device__ float g_as2[N_NODES];
__device__ float g_ad2[N_NODES];
__device__ int   g_deg[N_NODES];
__device__ int   g_off[N_NODES];
__device__ int   g_cur[N_NODES];
__device__ int   g_csr[E_EDGES];
__device__ int   g_bsum[CSR_BLOCKS];
__device__ int   g_bscan[CSR_BLOCKS];
__device__ __align__(16) float g_was2[F1];
__device__ __align__(16) float g_wad2[F1];
__device__ int   g_bar_count;
__device__ int   g_bar_gen;

__device__ __forceinline__ float lrelu(float v) { return v > 0.f ? v : 0.2f * v; }

// ---- packed fp32x2 helpers (sm_103a; PTX-only) -------------------------------
__device__ __forceinline__ unsigned long long packdup(float a) {
    unsigned long long r;
    asm("mov.b64 %0, {%1, %1};" : "=l"(r) : "f"(a));
    return r;
}
__device__ __forceinline__ void ffma2(unsigned long long& acc,
                                      unsigned long long a, unsigned long long b) {
    asm("fma.rn.f32x2 %0, %1, %2, %0;" : "+l"(acc) : "l"(a), "l"(b));
}
__device__ __forceinline__ float lo32(unsigned long long v) {
    return __uint_as_float((unsigned)(v & 0xffffffffull));
}
__device__ __forceinline__ float hi32(unsigned long long v) {
    return __uint_as_float((unsigned)(v >> 32));
}

// ---- software grid barrier (all CSR_BLOCKS co-resident by launch_bounds) ----
__device__ __forceinline__ void gsync() {
    __syncthreads();
    __threadfence();
    if (threadIdx.x == 0) {
        int gen = *(volatile int*)&g_bar_gen;
        if (atomicAdd(&g_bar_count, 1) == CSR_BLOCKS - 1) {
            g_bar_count = 0;
            __threadfence();
            *(volatile int*)&g_bar_gen = gen + 1;
        } else {
            while (*(volatile int*)&g_bar_gen == gen) { }
        }
        __threadfence();
    }
    __syncthreads();
}

// ---------------- fused CSR build: zero + degree + scan + scatter -------------
__global__ void __launch_bounds__(CSR_THREADS, 8)
k_csr(const int* __restrict__ src, const int* __restrict__ dst, int E, int n) {
    const int T = CSR_BLOCKS * CSR_THREADS;
    int t = threadIdx.x;
    int gt = blockIdx.x * CSR_THREADS + t;
    int lane = t & 31, w = t >> 5;
    __shared__ int wsum[8];

    // P0: zero degrees
    for (int i = gt; i < n; i += T) g_deg[i] = 0;
    gsync();
    // P1: count degrees
    for (int e = gt; e < E; e += T) atomicAdd(&g_deg[dst[e]], 1);
    gsync();
    // P2: per-thread chunk sum + block scan
    int C = (n + T - 1) / T;
    int b0 = gt * C;
    int s = 0;
    for (int i = 0; i < C; ++i) { int idx = b0 + i; if (idx < n) s += g_deg[idx]; }
    int incl = s;
    #pragma unroll
    for (int o = 1; o < 32; o <<= 1) {
        int xv = __shfl_up_sync(0xffffffffu, incl, o);
        if (lane >= o) incl += xv;
    }
    if (lane == 31) wsum[w] = incl;
    __syncthreads();
    if (t < 8) {
        int xv = wsum[t];
        #pragma unroll
        for (int o = 1; o < 8; o <<= 1) {
            int y = __shfl_up_sync(0xffu, xv, o);
            if (t >= o) xv += y;
        }
        wsum[t] = xv;
    }
    __syncthreads();
    int excl = incl - s + (w > 0 ? wsum[w - 1] : 0);
    if (t == CSR_THREADS - 1) g_bsum[blockIdx.x] = excl + s;
    gsync();
    // P3: block 0 scans block totals (512 totals, 2 per thread)
    if (blockIdx.x == 0) {
        int a0 = g_bsum[2 * t], a1 = g_bsum[2 * t + 1];
        int ss = a0 + a1;
        int in2 = ss;
        #pragma unroll
        for (int o = 1; o < 32; o <<= 1) {
            int xv = __shfl_up_sync(0xffffffffu, in2, o);
            if (lane >= o) in2 += xv;
        }
        if (lane == 31) wsum[w] = in2;
        __syncthreads();
        if (t < 8) {
            int xv = wsum[t];
            #pragma unroll
            for (int o = 1; o < 8; o <<= 1) {
                int y = __shfl_up_sync(0xffu, xv, o);
                if (t >= o) xv += y;
            }
            wsum[t] = xv;
        }
        __syncthreads();
        int ex2 = in2 - ss + (w > 0 ? wsum[w - 1] : 0);
        g_bscan[2 * t]     = ex2;
        g_bscan[2 * t + 1] = ex2 + a0;
    }
    gsync();
    // P4: write offsets
    int off = excl + g_bscan[blockIdx.x];
    for (int i = 0; i < C; ++i) {
        int idx = b0 + i;
        if (idx < n) { int d = g_deg[idx]; g_off[idx] = off; g_cur[idx] = off; off += d; }
    }
    gsync();
    // P5: scatter
    for (int e = gt; e < E; e += T) {
        int d = dst[e];
        int pos = atomicAdd(&g_cur[d], 1);
        g_csr[pos] = src[e];
    }
}

// ---------------- layer-2 attention fold only ---------------------------------
__global__ void k_fold2(const float* __restrict__ W2,
                        const float* __restrict__ as2, const float* __restrict__ ad2) {
    int t = threadIdx.x;  // 128
    float s = 0.f, d = 0.f;
    for (int c = 0; c < OUTC; ++c) {
        float w = W2[t * OUTC + c];
        s += w * as2[c];
        d += w * ad2[c];
    }
    g_was2[t] = s;
    g_wad2[t] = d;
}

// ---------------- layer-1 projection + logits ---------------------------------
__global__ void k1_proj(const float* __restrict__ x, const float* __restrict__ W1,
                        const float* __restrict__ attS, const float* __restrict__ attD, int n) {
    __shared__ __align__(16) float Ws[IN_DIM * F1];     // 16 KB
    __shared__ __align__(16) float xsT[IN_DIM][36];
    int t = threadIdx.x;                                // 256
    for (int i = t; i < IN_DIM * F1; i += 256) Ws[i] = W1[i];
    int base = blockIdx.x * 32;
    #pragma unroll
    for (int i = 0; i < 4; ++i) {
        int idx = t + i * 256;
        int node = idx >> 5, k = idx & 31;
        int nn = base + node;
        xsT[k][node] = (nn < n) ? x[(size_t)nn * IN_DIM + k] : 0.f;
    }
    __syncthreads();
    int tx = t & 31;        // cols tx*4 .. +3
    int ty = t >> 5;        // nodes ty*4 .. +3 (warp == ty)
    unsigned long long acc[4][2] = {};
    #pragma unroll
    for (int k = 0; k < IN_DIM; ++k) {
        ulonglong2 w = *(const ulonglong2*)&Ws[k * F1 + tx * 4];
        float4 xv = *(const float4*)&xsT[k][ty * 4];
        unsigned long long xp0 = packdup(xv.x), xp1 = packdup(xv.y);
        unsigned long long xp2 = packdup(xv.z), xp3 = packdup(xv.w);
        ffma2(acc[0][0], w.x, xp0); ffma2(acc[0][1], w.y, xp0);
        ffma2(acc[1][0], w.x, xp1); ffma2(acc[1][1], w.y, xp1);
        ffma2(acc[2][0], w.x, xp2); ffma2(acc[2][1], w.y, xp2);
        ffma2(acc[3][0], w.x, xp3); ffma2(acc[3][1], w.y, xp3);
    }
    // att vectors: att[h][c] contiguous; col = h*64+c maps 1:1
    float4 av = __ldg((const float4*)&attS[tx * 4]);
    float4 dv = __ldg((const float4*)&attD[tx * 4]);
    #pragma unroll
    for (int i = 0; i < 4; ++i) {
        int nn = base + ty * 4 + i;
        float f0 = lo32(acc[i][0]), f1 = hi32(acc[i][0]);
        float f2 = lo32(acc[i][1]), f3 = hi32(acc[i][1]);
        if (nn < n) {
            __half2 p01 = __floats2half2_rn(f0, f1);
            __half2 p23 = __floats2half2_rn(f2, f3);
            uint2 u;
            u.x = reinterpret_cast<unsigned&>(p01);
            u.y = reinterpret_cast<unsigned&>(p23);
            *(uint2*)(g_h1h + (size_t)nn * F1 + tx * 4) = u;
        }
        float ps = f0 * av.x + f1 * av.y + f2 * av.z + f3 * av.w;
        float pd = f0 * dv.x + f1 * dv.y + f2 * dv.z + f3 * dv.w;
        // reduce within 16-lane half (one head per half-warp)
        #pragma unroll
        for (int o = 8; o > 0; o >>= 1) {
            ps += __shfl_xor_sync(0xffffffffu, ps, o);
            pd += __shfl_xor_sync(0xffffffffu, pd, o);
        }
        if ((tx & 15) == 0 && nn < n) {
            g_as1[2 * nn + (tx >> 4)] = ps;
            g_ad1[2 * nn + (tx >> 4)] = pd;
        }
    }
}

// ------- layer-1 gather + normalize + LN + ReLU + layer-2 logits (fused) -----
// lane owns channels 4*lane..4*lane+3; head = lane>>4
__global__ void k_gather1(const float* __restrict__ bias1,
                          const float* __restrict__ gamma,
                          const float* __restrict__ beta, int n) {
    int node = (blockIdx.x * blockDim.x + threadIdx.x) >> 5;
    if (node >= n) return;
    int lane = threadIdx.x & 31;
    int h = lane >> 4;
    float lad = g_ad1[2 * node + h];
    float a0 = 0.f, a1 = 0.f, a2 = 0.f, a3 = 0.f, s = 0.f;
    float b0 = 0.f, b1 = 0.f, b2 = 0.f, b3 = 0.f, s2 = 0.f;
    // self-loop
    {
        float wv = __expf(lrelu(g_as1[2 * node + h] + lad));
        uint2 r = *(const uint2*)(g_h1h + (size_t)node * F1 + 4 * lane);
        float2 fA = __half22float2(reinterpret_cast<__half2&>(r.x));
        float2 fB = __half22float2(reinterpret_cast<__half2&>(r.y));
        a0 += wv * fA.x; a1 += wv * fA.y; a2 += wv * fB.x; a3 += wv * fB.y; s += wv;
    }
    int e = g_off[node], end = g_cur[node];
    for (; e + 1 < end; e += 2) {
        int sA = g_csr[e], sB = g_csr[e + 1];
        float eA = g_as1[2 * sA + h];
        float eB = g_as1[2 * sB + h];
        uint2 rA = *(const uint2*)(g_h1h + (size_t)sA * F1 + 4 * lane);
        uint2 rB = *(const uint2*)(g_h1h + (size_t)sB * F1 + 4 * lane);
        float wA = __expf(lrelu(eA + lad));
        float wB = __expf(lrelu(eB + lad));
        float2 fA0 = __half22float2(reinterpret_cast<__half2&>(rA.x));
        float2 fA1 = __half22float2(reinterpret_cast<__half2&>(rA.y));
        float2 fB0 = __half22float2(reinterpret_cast<__half2&>(rB.x));
        float2 fB1 = __half22float2(reinterpret_cast<__half2&>(rB.y));
        a0 += wA * fA0.x; a1 += wA * fA0.y; a2 += wA * fA1.x; a3 += wA * fA1.y; s += wA;
        b0 += wB * fB0.x; b1 += wB * fB0.y; b2 += wB * fB1.x; b3 += wB * fB1.y; s2 += wB;
    }
    if (e < end) {
        int sA = g_csr[e];
        float wv = __expf(lrelu(g_as1[2 * sA + h] + lad));
        uint2 r = *(const uint2*)(g_h1h + (size_t)sA * F1 + 4 * lane);
        float2 fA = __half22float2(reinterpret_cast<__half2&>(r.x));
        float2 fB = __half22float2(reinterpret_cast<__half2&>(r.y));
        a0 += wv * fA.x; a1 += wv * fA.y; a2 += wv * fB.x; a3 += wv * fB.y; s += wv;
    }
    a0 += b0; a1 += b1; a2 += b2; a3 += b3; s += s2;

    int c = 4 * lane;
    float r = 1.f / s;
    float4 bi = *(const float4*)&bias1[c];
    float v0 = a0 * r + bi.x;
    float v1 = a1 * r + bi.y;
    float v2 = a2 * r + bi.z;
    float v3 = a3 * r + bi.w;
    // LayerNorm over 128 channels
    float tot = v0 + v1 + v2 + v3;
    #pragma unroll
    for (int o = 16; o > 0; o >>= 1) tot += __shfl_xor_sync(0xffffffffu, tot, o);
    float mu = tot * (1.f / 128.f);
    float d0 = v0 - mu, d1 = v1 - mu, d2 = v2 - mu, d3 = v3 - mu;
    float sq = d0 * d0 + d1 * d1 + d2 * d2 + d3 * d3;
    #pragma unroll
    for (int o = 16; o > 0; o >>= 1) sq += __shfl_xor_sync(0xffffffffu, sq, o);
    float inv = rsqrtf(sq * (1.f / 128.f) + 1e-5f);
    float4 gm = *(const float4*)&gamma[c];
    float4 bt = *(const float4*)&beta[c];
    float y0 = fmaxf(d0 * inv * gm.x + bt.x, 0.f);
    float y1 = fmaxf(d1 * inv * gm.y + bt.y, 0.f);
    float y2 = fmaxf(d2 * inv * gm.z + bt.z, 0.f);
    float y3 = fmaxf(d3 * inv * gm.w + bt.w, 0.f);
    {
        __half2 p01 = __floats2half2_rn(y0, y1);
        __half2 p23 = __floats2half2_rn(y2, y3);
        uint2 u;
        u.x = reinterpret_cast<unsigned&>(p01);
        u.y = reinterpret_cast<unsigned&>(p23);
        *(uint2*)(g_hlnh + (size_t)node * F1 + c) = u;
    }
    // layer-2 logits from registers
    float4 ws = *(const float4*)&g_was2[c];
    float4 wd = *(const float4*)&g_wad2[c];
    float sa = y0 * ws.x + y1 * ws.y + y2 * ws.z + y3 * ws.w;
    float sd = y0 * wd.x + y1 * wd.y + y2 * wd.z + y3 * wd.w;
    #pragma unroll
    for (int o = 16; o > 0; o >>= 1) {
        sa += __shfl_xor_sync(0xffffffffu, sa, o);
        sd += __shfl_xor_sync(0xffffffffu, sd, o);
    }
    if (lane == 0) { g_as2[node] = sa; g_ad2[node] = sd; }
}

// ---------------- layer-2 projection: h2(fp16) = hln(fp16) @ W2 --------------
__global__ void k4_proj(const float* __restrict__ W2, int n) {
    __shared__ __align__(16) float Ws[F1 * OUTC];       // 32 KB
    __shared__ __half2 xsT[F1 / 2][33];                 // 8.4 KB
    int t = threadIdx.x;                                // 128
    for (int i = t; i < F1 * OUTC; i += 128) Ws[i] = W2[i];
    int base = blockIdx.x * 32;
    #pragma unroll
    for (int i = 0; i < 16; ++i) {
        int idx = t + i * 128;
        int node = idx >> 6, kk = idx & 63;
        int nn = base + node;
        xsT[kk][node] = (nn < n) ? ((const __half2*)g_hlnh)[(size_t)nn * 64 + kk]
                                 : __float2half2_rn(0.f);
    }
    __syncthreads();
    int tx = t & 15;   // cols tx*4 .. +3
    int ty = t >> 4;   // nodes ty*4 .. +3
    unsigned long long acc[4][2] = {};
    #pragma unroll 4
    for (int kk = 0; kk < 64; ++kk) {
        ulonglong2 wA = *(const ulonglong2*)&Ws[(2 * kk)     * OUTC + tx * 4];
        ulonglong2 wB = *(const ulonglong2*)&Ws[(2 * kk + 1) * OUTC + tx * 4];
        #pragma unroll
        for (int i = 0; i < 4; ++i) {
            float2 f = __half22float2(xsT[kk][ty * 4 + i]);
            unsigned long long xp0 = packdup(f.x), xp1 = packdup(f.y);
            ffma2(acc[i][0], wA.x, xp0); ffma2(acc[i][0], wB.x, xp1);
            ffma2(acc[i][1], wA.y, xp0); ffma2(acc[i][1], wB.y, xp1);
        }
    }
    #pragma unroll
    for (int i = 0; i < 4; ++i) {
        int nn = base + ty * 4 + i;
        if (nn >= n) continue;
        __half2 p01 = __floats2half2_rn(lo32(acc[i][0]), hi32(acc[i][0]));
        __half2 p23 = __floats2half2_rn(lo32(acc[i][1]), hi32(acc[i][1]));
        uint2 u;
        u.x = reinterpret_cast<unsigned&>(p01);
        u.y = reinterpret_cast<unsigned&>(p23);
        *(uint2*)(g_h2h + (size_t)nn * OUTC + tx * 4) = u;
    }
}

// ---------------- layer-2 gather + finalize ----------------------------------
__global__ void k_gather2(float* __restrict__ out, const float* __restrict__ bias2, int n) {
    int node = (blockIdx.x * blockDim.x + threadIdx.x) >> 5;
    if (node >= n) return;
    int lane = threadIdx.x & 31;
    float lad = g_ad2[node];
    float ax = 0.f, ay = 0.f, ssum = 0.f;
    float bx = 0.f, by = 0.f, tsum = 0.f;
    {
        float w = __expf(lrelu(g_as2[node] + lad));
        float2 f = __half22float2(((const __half2*)(g_h2h + (size_t)node * OUTC))[lane]);
        ax += w * f.x; ay += w * f.y; ssum += w;
    }
    int e = g_off[node], end = g_cur[node];
    for (; e + 1 < end; e += 2) {
        int sA = g_csr[e], sB = g_csr[e + 1];
        float lsA = g_as2[sA], lsB = g_as2[sB];
        __half2 rA = ((const __half2*)(g_h2h + (size_t)sA * OUTC))[lane];
        __half2 rB = ((const __half2*)(g_h2h + (size_t)sB * OUTC))[lane];
        float wA = __expf(lrelu(lsA + lad));
        float wB = __expf(lrelu(lsB + lad));
        float2 fA = __half22float2(rA), fB = __half22float2(rB);
        ax += wA * fA.x; ay += wA * fA.y; ssum += wA;
        bx += wB * fB.x; by += wB * fB.y; tsum += wB;
    }
    if (e < end) {
        int sA = g_csr[e];
        float w = __expf(lrelu(g_as2[sA] + lad));
        float2 f = __half22float2(((const __half2*)(g_h2h + (size_t)sA * OUTC))[lane]);
        ax += w * f.x; ay += w * f.y; ssum += w;
    }
    ax += bx; ay += by; ssum += tsum;
    float r = 1.f / ssum;
    float2 o;
    o.x = ax * r + bias2[2 * lane];
    o.y = ay * r + bias2[2 * lane + 1];
    ((float2*)out)[(size_t)node * 32 + lane] = o;
}

// ---------------- launcher -----------------------------------------------------
extern "C" void kernel_launch(void* const* d_in, const int* in_sizes, int n_in,
                              void* d_out, int out_size) {
    const float* x     = (const float*)d_in[0];
    const int*   ei    = (const int*)  d_in[1];
    const float* W1    = (const float*)d_in[2];
    const float* as1   = (const float*)d_in[3];
    const float* ad1   = (const float*)d_in[4];
    const float* b1    = (const float*)d_in[5];
    const float* gamma = (const float*)d_in[6];
    const float* beta  = (const float*)d_in[7];
    const float* W2    = (const float*)d_in[8];
    const float* as2   = (const float*)d_in[9];
    const float* ad2   = (const float*)d_in[10];
    const float* b2    = (const float*)d_in[11];
    float* out = (float*)d_out;

    int n = in_sizes[0] / IN_DIM;
    int E = in_sizes[1] / 2;
    const int* srcp = ei;
    const int* dstp = ei + E;

    k_csr<<<CSR_BLOCKS, CSR_THREADS>>>(srcp, dstp, E, n);          // 1
    k_fold2<<<1, 128>>>(W2, as2, ad2);                             // 2
    k1_proj<<<(n + 31) / 32, 256>>>(x, W1, as1, ad1, n);           // 3
    k_gather1<<<(n + 7) / 8, 256>>>(b1, gamma, beta, n);           // 4 <- profiled
    k4_proj<<<(n + 31) / 32, 128>>>(W2, n);                        // 5
    k_gather2<<<(n + 7) / 8, 256>>>(out, b2, n);                   // 6
}